// round 2
// baseline (speedup 1.0000x reference)
#include <cuda_runtime.h>

// Conv2D: x[4096,4096] fp32, w[15,15], valid -> out[4082,4082] + bias.
//
// Round 2: input-row reuse. Iterate over input rows t; each row feeds RY=3
// accumulator rows (ky = t - r). Rotating 3-row weight register window.
// Tile 256x24, thread computes two 4-wide groups (left/right 128-halves) x 3
// rows = 24 outputs. All shared loads are 16B-stride conflict-free LDS.128.

#define HI 4096
#define WI 4096
#define KH 15
#define KW 15
#define OH (HI - KH + 1)   // 4082
#define OW (WI - KW + 1)   // 4082

#define TOX 256            // output tile width (two 128-wide halves)
#define TOY 24             // output tile height
#define RY  3              // rows per thread
#define NTHREADS 256

#define IN_ROWS (TOY + KH - 1)   // 38
#define IN_COLS (TOX + KW - 1)   // 270
#define PITCH   272              // padded row (floats), 16B-aligned

__global__ __launch_bounds__(NTHREADS, 2)
void conv2d_rowreuse_kernel(const float* __restrict__ x,
                            const float* __restrict__ w,
                            const float* __restrict__ bias,
                            float* __restrict__ out)
{
    __shared__ float s_in[IN_ROWS][PITCH];   // 38*272*4 = 41344 B
    __shared__ float s_w[KH * KW];

    const int tid = threadIdx.x;
    const int ox0 = blockIdx.x * TOX;
    const int oy0 = blockIdx.y * TOY;

    // ---- Stage weights ----
    if (tid < KH * KW) s_w[tid] = w[tid];

    // ---- Stage input tile as float4 chunks (zero-fill OOB) ----
    // 38 rows x 68 float4 per row (covers 272 >= 270 cols).
    #pragma unroll 2
    for (int i = tid; i < IN_ROWS * 68; i += NTHREADS) {
        const int rr = i / 68;
        const int cc = (i - rr * 68) * 4;
        const int gy = oy0 + rr;
        const int gx = ox0 + cc;
        float4 v = make_float4(0.f, 0.f, 0.f, 0.f);
        if (gy < HI) {
            if (gx + 3 < WI) {
                v = *reinterpret_cast<const float4*>(&x[(long)gy * WI + gx]);
            } else {
                if (gx + 0 < WI) v.x = x[(long)gy * WI + gx + 0];
                if (gx + 1 < WI) v.y = x[(long)gy * WI + gx + 1];
                if (gx + 2 < WI) v.z = x[(long)gy * WI + gx + 2];
                if (gx + 3 < WI) v.w = x[(long)gy * WI + gx + 3];
            }
        }
        *reinterpret_cast<float4*>(&s_in[rr][cc]) = v;
    }
    __syncthreads();

    const int tx = tid & 31;   // x within half (each thread: 4-wide group)
    const int ty = tid >> 5;   // 0..7 -> y strip of 3 rows

    float accL[RY][4], accR[RY][4];
    #pragma unroll
    for (int r = 0; r < RY; ++r)
        #pragma unroll
        for (int j = 0; j < 4; ++j) { accL[r][j] = 0.f; accR[r][j] = 0.f; }

    float wk[RY][KW];   // rotating weight-row window (rows t-2..t)

    #pragma unroll
    for (int t = 0; t < RY + KH - 1; ++t) {   // 17 input rows per thread-strip
        if (t < KH) {
            #pragma unroll
            for (int kx = 0; kx < KW; ++kx)
                wk[t % RY][kx] = s_w[t * KW + kx];
        }

        const float* rp = &s_in[ty * RY + t][0];

        // ---- Left half ----
        {
            float a[20];
            #pragma unroll
            for (int q = 0; q < 5; ++q) {
                const float4 v = *reinterpret_cast<const float4*>(&rp[tx * 4 + 4 * q]);
                a[4 * q + 0] = v.x; a[4 * q + 1] = v.y;
                a[4 * q + 2] = v.z; a[4 * q + 3] = v.w;
            }
            #pragma unroll
            for (int r = 0; r < RY; ++r) {
                if (r <= t && t - r < KH) {            // compile-time after unroll
                    const int ky = t - r;
                    #pragma unroll
                    for (int kx = 0; kx < KW; ++kx) {
                        const float wv = wk[ky % RY][kx];
                        #pragma unroll
                        for (int j = 0; j < 4; ++j)
                            accL[r][j] = fmaf(wv, a[kx + j], accL[r][j]);
                    }
                }
            }
        }
        // ---- Right half (+128 cols) ----
        {
            float a[20];
            #pragma unroll
            for (int q = 0; q < 5; ++q) {
                const float4 v = *reinterpret_cast<const float4*>(&rp[128 + tx * 4 + 4 * q]);
                a[4 * q + 0] = v.x; a[4 * q + 1] = v.y;
                a[4 * q + 2] = v.z; a[4 * q + 3] = v.w;
            }
            #pragma unroll
            for (int r = 0; r < RY; ++r) {
                if (r <= t && t - r < KH) {
                    const int ky = t - r;
                    #pragma unroll
                    for (int kx = 0; kx < KW; ++kx) {
                        const float wv = wk[ky % RY][kx];
                        #pragma unroll
                        for (int j = 0; j < 4; ++j)
                            accR[r][j] = fmaf(wv, a[kx + j], accR[r][j]);
                    }
                }
            }
        }
    }

    // ---- Epilogue: bias + float2 stores (8B-aligned since OW even) ----
    const float b = __ldg(&bias[0]);
    #pragma unroll
    for (int r = 0; r < RY; ++r) {
        const int oy = oy0 + ty * RY + r;
        if (oy >= OH) continue;
        float* orow = &out[(long)oy * OW];
        // Left half: ox <= 3840+127 = 3967 < OW always.
        {
            const int ox = ox0 + tx * 4;
            #pragma unroll
            for (int p = 0; p < 2; ++p) {
                float2 v = make_float2(accL[r][2 * p] + b, accL[r][2 * p + 1] + b);
                *reinterpret_cast<float2*>(&orow[ox + 2 * p]) = v;
            }
        }
        // Right half: needs guard (OW even -> pairs never straddle the edge).
        {
            const int ox = ox0 + 128 + tx * 4;
            #pragma unroll
            for (int p = 0; p < 2; ++p) {
                if (ox + 2 * p + 1 < OW) {
                    float2 v = make_float2(accR[r][2 * p] + b, accR[r][2 * p + 1] + b);
                    *reinterpret_cast<float2*>(&orow[ox + 2 * p]) = v;
                }
            }
        }
    }
}

extern "C" void kernel_launch(void* const* d_in, const int* in_sizes, int n_in,
                              void* d_out, int out_size)
{
    const float* x    = (const float*)d_in[0];
    const float* w    = (const float*)d_in[1];
    const float* bias = (const float*)d_in[2];
    float* out        = (float*)d_out;

    dim3 grid((OW + TOX - 1) / TOX,   // 16
              (OH + TOY - 1) / TOY);  // 171
    conv2d_rowreuse_kernel<<<grid, NTHREADS>>>(x, w, bias, out);
}

// round 4
// speedup vs baseline: 1.2169x; 1.2169x over previous
#include <cuda_runtime.h>

// Conv2D: x[4096,4096] fp32, w[15,15], valid -> out[4082,4082] + bias.
//
// Round 4 = Round 3 with the store-alignment bug fixed:
// out rows (stride 4082 floats) are only 8B-aligned on odd rows, so the
// epilogue must use float2 (STG.64), not float4.
//
//  - 128-thread CTA, tile 128(x) x 24(y). Thread: 8 cols x 3 rows = 24 outputs.
//  - Iterate input rows t=0..16; each row feeds up to 3 accumulator rows
//    (ky = t - r). Weight rows in rotating 3-slot register window, statically
//    indexed via unroll-by-3.
//  - t-loop rolled (6 outer iters) -> body fits L1.5 I$.

#define HI 4096
#define WI 4096
#define KH 15
#define KW 15
#define OH (HI - KH + 1)   // 4082
#define OW (WI - KW + 1)   // 4082

#define TOX 128            // output tile width  (16 threads x RX=8)
#define TOY 24             // output tile height (8 strips x RY=3)
#define RX  8
#define RY  3
#define NT  128

#define IN_ROWS (TOY + KH - 1)   // 38
#define PITCH   144              // floats per smem row (16B-aligned)

__global__ __launch_bounds__(NT, 4)
void conv2d_v4_kernel(const float* __restrict__ x,
                      const float* __restrict__ w,
                      const float* __restrict__ bias,
                      float* __restrict__ out)
{
    __shared__ float s_in[IN_ROWS][PITCH];   // 21.9 KB
    __shared__ float s_w[KH * KW];

    const int tid = threadIdx.x;
    const int ox0 = blockIdx.x * TOX;
    const int oy0 = blockIdx.y * TOY;

    // ---- Stage weights ----
    #pragma unroll
    for (int i = tid; i < KH * KW; i += NT) s_w[i] = w[i];

    // ---- Stage input tile as float4 (38 rows x 36 float4) ----
    // ox0 multiple of 128, WI%4==0 -> each float4 fully in- or out-of-range.
    #pragma unroll 2
    for (int i = tid; i < IN_ROWS * 36; i += NT) {
        const int r  = i / 36;
        const int c  = (i - r * 36) * 4;
        const int gy = oy0 + r;
        const int gx = ox0 + c;
        float4 v = make_float4(0.f, 0.f, 0.f, 0.f);
        if (gy < HI && gx < WI)
            v = *reinterpret_cast<const float4*>(&x[(long)gy * WI + gx]);
        *reinterpret_cast<float4*>(&s_in[r][c]) = v;
    }
    __syncthreads();

    const int tx = tid & 15;   // column group (8 wide)
    const int ty = tid >> 4;   // row strip (3 rows)

    float acc[RY][RX];
    #pragma unroll
    for (int r = 0; r < RY; ++r)
        #pragma unroll
        for (int j = 0; j < RX; ++j) acc[r][j] = 0.f;

    float wk[3][KW];           // rotating weight-row window, slot = ky % 3

    // t = 0..16, processed in 6 groups of 3 so the window slot
    // (t - r) % 3 == (c - r) % 3 is a compile-time constant.
    #pragma unroll 1
    for (int u = 0; u < 6; ++u) {
        #pragma unroll
        for (int c = 0; c < 3; ++c) {
            const int t = 3 * u + c;
            if (t < RY + KH - 1) {                 // skip t == 17
                if (t < KH) {                      // load weight row t -> slot c
                    #pragma unroll
                    for (int kx = 0; kx < KW; ++kx)
                        wk[c][kx] = s_w[t * KW + kx];
                }

                // 24 input floats (need 22) via 6 conflict-free LDS.128.
                float a[24];
                const float* rp = &s_in[ty * RY + t][tx * RX];
                #pragma unroll
                for (int q = 0; q < 6; ++q) {
                    const float4 v = *reinterpret_cast<const float4*>(rp + 4 * q);
                    a[4 * q + 0] = v.x; a[4 * q + 1] = v.y;
                    a[4 * q + 2] = v.z; a[4 * q + 3] = v.w;
                }

                #pragma unroll
                for (int r = 0; r < RY; ++r) {
                    if ((unsigned)(t - r) < (unsigned)KH) {     // ky in range
                        const int slot = ((c - r) % 3 + 3) % 3; // compile-time
                        #pragma unroll
                        for (int kx = 0; kx < KW; ++kx) {
                            const float wv = wk[slot][kx];
                            #pragma unroll
                            for (int j = 0; j < RX; ++j)
                                acc[r][j] = fmaf(wv, a[kx + j], acc[r][j]);
                        }
                    }
                }
            }
        }
    }

    // ---- Epilogue: bias + float2 stores (8B-aligned: OW even, ox even) ----
    const float b = __ldg(&bias[0]);
    #pragma unroll
    for (int r = 0; r < RY; ++r) {
        const int oy = oy0 + ty * RY + r;
        if (oy >= OH) continue;
        float* orow = &out[(long)oy * OW];
        #pragma unroll
        for (int p = 0; p < 4; ++p) {
            const int ox = ox0 + tx * RX + 2 * p;
            if (ox + 1 < OW) {    // OW even, ox even -> pair never straddles
                float2 v = make_float2(acc[r][2 * p] + b, acc[r][2 * p + 1] + b);
                *reinterpret_cast<float2*>(&orow[ox]) = v;
            }
        }
    }
}

extern "C" void kernel_launch(void* const* d_in, const int* in_sizes, int n_in,
                              void* d_out, int out_size)
{
    const float* x    = (const float*)d_in[0];
    const float* w    = (const float*)d_in[1];
    const float* bias = (const float*)d_in[2];
    float* out        = (float*)d_out;

    dim3 grid((OW + TOX - 1) / TOX,   // 32
              (OH + TOY - 1) / TOY);  // 171
    conv2d_v4_kernel<<<grid, NT>>>(x, w, bias, out);
}